// round 12
// baseline (speedup 1.0000x reference)
#include <cuda_runtime.h>
#include <cuda_bf16.h>

#define BB 4
#define NN 261888
#define NH (NN / 2)
#define PP 6000
#define NP 2000
#define NBINS 65536
#define CAP 16384
#define NW 94          // ceil(PP/64)
#define NWPAD 96       // padded gmem row (16B aligned)
#define SEGCAP 4096
#define DPAD 6016      // NW*64
#define NCTA 148
#define NTH 1024
#define NS 8
#define HBASE 0x3C00   // smem-privatized bins: scores >= 2^-7
#define HSPAN 4096
#define BLK1 40        // speculative NMS window (2560 candidates)

typedef unsigned long long u64;

// ---------------- scratch (device globals; no allocations) ----------------
__device__ unsigned int        g_hist[BB][NBINS];
__device__ unsigned int        g_cursor[BB][NBINS];
__device__ int                 g_thresh[BB];
__device__ unsigned int        g_barrier[NS];     // zero-init; self-resetting
__device__ u64                 g_cand[BB][CAP];
__device__ __align__(16) float4 g_boxes[BB][PP];
__device__ float               g_area[BB][PP];
__device__ __align__(16) u64   g_supp[BB][PP][NWPAD];
__device__ __align__(16) u64   g_diag[BB][PP];
__device__ __align__(16) u64   g_rownz[BB][NW];
__device__ u64                 g_removed[BB][NW];
__device__ u64                 g_keptmask[BB][NW];
__device__ int                 g_done[BB];
__device__ int                 g_base[BB];

__device__ __forceinline__ int hslot(int bin) {
    return ((bin & 31) << 11) | (bin >> 5);
}

// grid barrier over NCTA co-resident CTAs; CTA0 resets slot s-1 after passing s
__device__ __forceinline__ void gbar(int s) {
    __syncthreads();
    if (threadIdx.x == 0) {
        __threadfence();
        atomicAdd(&g_barrier[s], 1u);
        while (((volatile unsigned*)g_barrier)[s] < NCTA) __nanosleep(64);
        __threadfence();
        if (blockIdx.x == 0 && s > 0) atomicExch(&g_barrier[s - 1], 0u);
    }
    __syncthreads();
}

// one tile of the suppression-mask computation
__device__ __forceinline__ void mask_tile(int b, int ib, int jb, int tid,
                                          float4* bj, float* aj) {
    int i = ib * 64 + (tid & 63);
    int j0 = jb * 64;
    if (tid < 64) {
        int jt = j0 + tid;
        if (jt < PP) { bj[tid] = g_boxes[b][jt]; aj[tid] = g_area[b][jt]; }
    }
    __syncthreads();
    if (jb >= ib && i < PP) {
        float4 bi = g_boxes[b][i];
        float  ai = g_area[b][i];
        u64 mask = 0ull;
        int jmax = min(64, PP - j0);
        #pragma unroll 4
        for (int jj = 0; jj < jmax; jj++) {
            if (j0 + jj <= i) continue;
            float4 bx = bj[jj];
            float iy1 = fmaxf(bi.x, bx.x), ix1 = fmaxf(bi.y, bx.y);
            float iy2 = fminf(bi.z, bx.z), ix2 = fminf(bi.w, bx.w);
            float ih = fmaxf(iy2 - iy1, 0.f), iw = fmaxf(ix2 - ix1, 0.f);
            float inter = ih * iw;
            float uni = ai + aj[jj] - inter;
            if (inter > 0.7f * fmaxf(uni, 1e-8f)) mask |= (1ull << jj);
        }
        if (jb == ib) {
            g_diag[b][i] = mask;
        } else {
            g_supp[b][i][jb] = mask;
            if (mask) atomicOr(&g_rownz[b][ib], 1ull << (i & 63));
        }
    }
    __syncthreads();
}

__global__ void __launch_bounds__(NTH, 1)
k_all(const float* __restrict__ rpn_class,
      const float* __restrict__ rpn_bbox,
      const float* __restrict__ anchors,
      float* __restrict__ out) {
    extern __shared__ u64 sh[];
    const int cta = blockIdx.x, tid = threadIdx.x;
    const int gtid = cta * NTH + tid;
    const int GT = NCTA * NTH;
    const int bb = cta & 3, cs = cta >> 2;

    // ---- phase 0: init persistent state; reset terminal barrier slots ----
    if (cta == 0 && tid == 0) { atomicExch(&g_barrier[6], 0u); atomicExch(&g_barrier[7], 0u); }
    for (int x = gtid; x < BB * NBINS; x += GT) ((unsigned*)g_hist)[x] = 0u;
    for (int x = gtid; x < BB * NW; x += GT) ((u64*)g_rownz)[x] = 0ull;
    if (gtid < BB) { g_thresh[gtid] = NBINS; g_done[gtid] = 0; }
    gbar(0);

    // ---- phase 1: histogram (smem-privatized hot bins) ----
    {
        unsigned* hh = (unsigned*)sh;
        for (int x = tid; x < HSPAN; x += NTH) hh[x] = 0u;
        __syncthreads();
        for (int i = cs * NTH + tid; i < NH; i += 37 * NTH) {
            float4 v = *(const float4*)(rpn_class + (size_t)bb * NN * 2 + (size_t)i * 4);
            unsigned b0 = __float_as_uint(v.y) >> 16;
            unsigned b1 = __float_as_uint(v.w) >> 16;
            if (b0 >= HBASE) atomicAdd(&hh[b0 - HBASE], 1u);
            else             atomicAdd(&g_hist[bb][hslot(b0)], 1u);
            if (b1 >= HBASE) atomicAdd(&hh[b1 - HBASE], 1u);
            else             atomicAdd(&g_hist[bb][hslot(b1)], 1u);
        }
        __syncthreads();
        for (int x = tid; x < HSPAN; x += NTH) {
            unsigned c = hh[x];
            if (c) atomicAdd(&g_hist[bb][hslot(HBASE + x)], c);
        }
    }
    gbar(1);

    // ---- phase 2: descending prefix sum, cursor bases, threshold ----
    if (cta < BB) {
        int b = cta;
        unsigned* gs = (unsigned*)sh;
        unsigned s = 0;
        #pragma unroll 8
        for (int k = 0; k < 64; k++) s += g_hist[b][hslot(tid * 64 + k)];
        gs[tid] = s;
        __syncthreads();
        unsigned self = s;
        for (int off = 1; off < 1024; off <<= 1) {
            unsigned v = (tid + off < 1024) ? gs[tid + off] : 0u;
            __syncthreads();
            gs[tid] += v;
            __syncthreads();
        }
        unsigned run = gs[tid] - self;
        int minbin = NBINS;
        for (int k = 63; k >= 0; k--) {
            int bin = tid * 64 + k;
            int hs = hslot(bin);
            g_cursor[b][hs] = run;
            if (run < PP) minbin = bin;
            run += g_hist[b][hs];
        }
        if (minbin < NBINS) atomicMin(&g_thresh[b], minbin);
    }
    gbar(2);

    // ---- phase 3: scatter candidates grouped by bin ----
    {
        int th = g_thresh[bb];
        for (int i = cs * NTH + tid; i < NH; i += 37 * NTH) {
            float4 v = *(const float4*)(rpn_class + (size_t)bb * NN * 2 + (size_t)i * 4);
            unsigned bits0 = __float_as_uint(v.y);
            unsigned bits1 = __float_as_uint(v.w);
            if ((int)(bits0 >> 16) >= th) {
                unsigned pos = atomicAdd(&g_cursor[bb][hslot(bits0 >> 16)], 1u);
                if (pos < CAP)
                    g_cand[bb][pos] = ((u64)bits0 << 32) | (u64)(0xFFFFFFFFu - (unsigned)(2 * i));
            }
            if ((int)(bits1 >> 16) >= th) {
                unsigned pos = atomicAdd(&g_cursor[bb][hslot(bits1 >> 16)], 1u);
                if (pos < CAP)
                    g_cand[bb][pos] = ((u64)bits1 << 32) | (u64)(0xFFFFFFFFu - (unsigned)(2 * i + 1));
            }
        }
    }
    gbar(3);

    // ---- phase 4: per-bin rank-by-count + fused decode ----
    for (int slot = cta; slot < BB * 64; slot += NCTA) {
        int b = slot >> 6, binoff = slot & 63;
        int bin = g_thresh[b] + binoff;
        if (bin >= NBINS) continue;
        int hs = hslot(bin);
        unsigned cnt = g_hist[b][hs];
        if (cnt == 0) continue;
        unsigned base = g_cursor[b][hs] - cnt;
        if (base >= PP) continue;
        unsigned cc = cnt < (unsigned)SEGCAP ? cnt : (unsigned)SEGCAP;
        u64* key = sh;
        for (unsigned x = tid; x < cc; x += NTH) key[x] = g_cand[b][base + x];
        __syncthreads();
        for (unsigned x = tid; x < cc; x += NTH) {
            u64 me = key[x];
            unsigned rank = 0;
            for (unsigned y = 0; y < cc; y++) rank += (key[y] > me);
            unsigned p = base + rank;
            if (p >= PP) continue;
            unsigned idx = 0xFFFFFFFFu - (unsigned)(me & 0xFFFFFFFFull);
            float4 a = *(const float4*)(anchors + (size_t)idx * 4);
            float4 d = *(const float4*)(rpn_bbox + ((size_t)b * NN + idx) * 4);
            d.x *= 0.1f; d.y *= 0.1f; d.z *= 0.2f; d.w *= 0.2f;
            float h = a.z - a.x, w = a.w - a.y;
            float cy = a.x + 0.5f * h, cx = a.y + 0.5f * w;
            cy = cy + d.x * h;
            cx = cx + d.y * w;
            h = h * expf(d.z);
            w = w * expf(d.w);
            float y1 = cy - 0.5f * h, x1 = cx - 0.5f * w;
            float y2 = cy + 0.5f * h, x2 = cx + 0.5f * w;
            y1 = fminf(fmaxf(y1, 0.f), 1024.f);
            x1 = fminf(fmaxf(x1, 0.f), 1024.f);
            y2 = fminf(fmaxf(y2, 0.f), 1024.f);
            x2 = fminf(fmaxf(x2, 0.f), 1024.f);
            const float inv = 1.0f / 1024.0f;
            float4 o = make_float4(y1 * inv, x1 * inv, y2 * inv, x2 * inv);
            g_boxes[b][p] = o;
            g_area[b][p] = (o.z - o.x) * (o.w - o.y);
        }
        __syncthreads();
    }
    gbar(4);

    // ---- phase 5a: mask tiles for the speculative window (ib<=jb<BLK1) ----
    {
        float4* bj = (float4*)sh;
        float*  aj = (float*)(bj + 64);
        const int NIBG1 = (BLK1 + 15) / 16;           // 3
        const int PER_B = BLK1 * NIBG1;               // 120
        for (int st = cta; st < BB * PER_B; st += NCTA) {
            int b = st / PER_B;
            int r = st % PER_B;
            int jb = r / NIBG1, ibg = r % NIBG1;
            if (jb < ibg * 16) continue;
            mask_tile(b, ibg * 16 + (tid >> 6), jb, tid, bj, aj);
        }
    }
    gbar(5);

    // ---- phase 6a: speculative NMS over blocks [0, BLK1) ----
    if (cta < BB) {
        int b = cta;
        u64* s_diag = sh;
        u64* s_rownz = sh + DPAD;
        __shared__ u64 s_pre, s_kept;
        __shared__ unsigned s_nz[2];
        __shared__ int s_base, s_prev, s_stop;

        float4* ob = (float4*)(out + (size_t)b * NP * 4);
        for (int x = tid; x < NP; x += NTH) ob[x] = make_float4(0.f, 0.f, 0.f, 0.f);
        for (int x = tid; x < BLK1 * 64; x += NTH) s_diag[x] = g_diag[b][x];
        for (int x = tid; x < NW; x += NTH) s_rownz[x] = g_rownz[b][x];

        u64 acc = 0ull;
        if (tid == 0) { s_base = 0; s_stop = 0; }
        __syncthreads();

        for (int blk = 0; blk < BLK1; blk++) {
            if (tid < 64) {
                u64 d = s_diag[blk * 64 + tid];
                unsigned bal = __ballot_sync(0xffffffffu, d != 0ull);
                if ((tid & 31) == 0) s_nz[tid >> 5] = bal;
            }
            if (tid == blk) s_pre = acc;
            __syncthreads();

            if (tid == 0) {
                u64 jm = (u64)s_nz[0] | ((u64)s_nz[1] << 32);
                u64 alive = ~s_pre;
                while (jm) {
                    int j = __ffsll((long long)jm) - 1; jm &= jm - 1;
                    if ((alive >> j) & 1ull) alive &= ~s_diag[blk * 64 + j];
                }
                int cnt = __popcll(alive);
                int rem = NP - s_base;
                while (cnt > rem) {
                    alive &= ~(1ull << (63 - __clzll((long long)alive)));
                    cnt--;
                }
                s_kept = alive;
                g_keptmask[b][blk] = alive;
                s_prev = s_base;
                s_base += cnt;
                if (s_base >= NP) s_stop = 1;
            }
            __syncthreads();

            u64 km = s_kept;
            if (tid < 64 && ((km >> tid) & 1ull)) {
                u64 lowmask = (tid == 0) ? 0ull : (km & ((1ull << tid) - 1ull));
                ob[s_prev + __popcll(lowmask)] = g_boxes[b][blk * 64 + tid];
            }
            if (tid < BLK1 && tid > blk) {            // only columns < BLK1 are valid
                u64 nz = s_rownz[blk] & km;
                while (nz) {
                    int j = __ffsll((long long)nz) - 1; nz &= nz - 1;
                    acc |= g_supp[b][blk * 64 + j][tid];
                }
            }
            if (s_stop) break;
        }
        __syncthreads();
        if (tid < NW) g_removed[b][tid] = acc;        // tid>=BLK1 words are 0 (placeholder)
        if (tid == 0) { g_done[b] = s_stop; g_base[b] = s_base; }
    }
    gbar(6);

    // ---- all-done check (uniform across CTAs) ----
    {
        __shared__ int s_alldone;
        if (tid == 0)
            s_alldone = g_done[0] & g_done[1] & g_done[2] & g_done[3];
        __syncthreads();
        if (s_alldone) return;                        // common case
    }

    // ---- phase 7: remaining mask tiles (jb >= BLK1, ib <= jb) ----
    {
        float4* bj = (float4*)sh;
        float*  aj = (float*)(bj + 64);
        const int NIBG = (NW + 15) / 16;              // 6
        const int PER_B = (NW - BLK1) * NIBG;         // 324
        for (int st = cta; st < BB * PER_B; st += NCTA) {
            int b = st / PER_B;
            int r = st % PER_B;
            int jb = BLK1 + r / NIBG, ibg = r % NIBG;
            if (jb < ibg * 16) continue;
            mask_tile(b, ibg * 16 + (tid >> 6), jb, tid, bj, aj);
        }
    }
    gbar(7);
    if (cta >= BB) return;

    // ---- phase 8: NMS continuation over blocks [BLK1, NW) ----
    {
        int b = cta;
        u64* s_diag = sh;
        u64* s_rownz = sh + DPAD;
        __shared__ u64 s_pre, s_kept;
        __shared__ unsigned s_nz[2];
        __shared__ int s_base, s_prev, s_stop;

        float4* ob = (float4*)(out + (size_t)b * NP * 4);
        for (int x = tid; x < DPAD; x += NTH)
            s_diag[x] = (x < PP) ? g_diag[b][x] : 0ull;
        for (int x = tid; x < NW; x += NTH) s_rownz[x] = g_rownz[b][x];
        if (tid == 0) { s_base = g_base[b]; s_stop = g_done[b]; }
        __syncthreads();

        u64 acc = (tid < NW) ? g_removed[b][tid] : 0ull;
        if (tid >= BLK1 && tid < NW) {                // reconstruct high words
            for (int blk = 0; blk < BLK1; blk++) {
                u64 nz = s_rownz[blk] & g_keptmask[b][blk];
                while (nz) {
                    int j = __ffsll((long long)nz) - 1; nz &= nz - 1;
                    acc |= g_supp[b][blk * 64 + j][tid];
                }
            }
        }
        __syncthreads();

        for (int blk = BLK1; blk < NW && !s_stop; blk++) {
            if (tid < 64) {
                u64 d = s_diag[blk * 64 + tid];
                unsigned bal = __ballot_sync(0xffffffffu, d != 0ull);
                if ((tid & 31) == 0) s_nz[tid >> 5] = bal;
            }
            if (tid == blk) s_pre = acc;
            __syncthreads();

            if (tid == 0) {
                u64 jm = (u64)s_nz[0] | ((u64)s_nz[1] << 32);
                u64 alive = ~s_pre;
                if (blk == NW - 1) alive &= (1ull << (PP - (NW - 1) * 64)) - 1ull;
                while (jm) {
                    int j = __ffsll((long long)jm) - 1; jm &= jm - 1;
                    if ((alive >> j) & 1ull) alive &= ~s_diag[blk * 64 + j];
                }
                int cnt = __popcll(alive);
                int rem = NP - s_base;
                while (cnt > rem) {
                    alive &= ~(1ull << (63 - __clzll((long long)alive)));
                    cnt--;
                }
                s_kept = alive;
                s_prev = s_base;
                s_base += cnt;
                if (s_base >= NP) s_stop = 1;
            }
            __syncthreads();

            u64 km = s_kept;
            if (tid < 64 && ((km >> tid) & 1ull)) {
                u64 lowmask = (tid == 0) ? 0ull : (km & ((1ull << tid) - 1ull));
                ob[s_prev + __popcll(lowmask)] = g_boxes[b][blk * 64 + tid];
            }
            if (tid < NW && tid > blk) {
                u64 nz = s_rownz[blk] & km;
                while (nz) {
                    int j = __ffsll((long long)nz) - 1; nz &= nz - 1;
                    acc |= g_supp[b][blk * 64 + j][tid];
                }
            }
            __syncthreads();
        }
    }
}

// ---------------- launch ----------------
extern "C" void kernel_launch(void* const* d_in, const int* in_sizes, int n_in,
                              void* d_out, int out_size) {
    const float* rpn_class = (const float*)d_in[0];
    const float* rpn_bbox  = (const float*)d_in[1];
    const float* anchors   = (const float*)d_in[2];
    float* out = (float*)d_out;

    int smem = 131072;
    cudaFuncSetAttribute(k_all, cudaFuncAttributeMaxDynamicSharedMemorySize, smem);
    k_all<<<NCTA, NTH, smem>>>(rpn_class, rpn_bbox, anchors, out);
}